// round 7
// baseline (speedup 1.0000x reference)
#include <cuda_runtime.h>

#define Bn 16
#define Cn 20
#define Hn 512
#define Wn 512
#define W4n (Wn / 4)
#define HWn (Hn * Wn)
#define HW4n (Hn * W4n)
#define CHWn (Cn * HWn)
#define HMASK (Hn - 1)
#define W4MASK (W4n - 1)

// Scratch (__device__ globals per allocation-free rule)
__device__ unsigned g_a1[Bn * HW4n];    // step-1 mask, 1 byte/pixel (0/1)
__device__ unsigned g_e1[Bn * HW4n];    // (world1 ch0 == 3) flag, packed
__device__ float4   g_d1[Bn * HW4n];    // world1 ch1 (density after step 1)
__device__ unsigned g_code[Bn * HW4n];  // per byte: a1[h] | a1[h+1]<<1 | a2[h]<<2 | a2[h+1]<<3

// exact 0/1-coefficient blend, BRANCHLESS: (1-a)(1-b)y + a*x + b*z
__device__ __forceinline__ float selv(bool a, bool b, float x, float y, float z) {
    float t = b ? z : y;
    t = a ? x : t;
    return (a && b) ? (x + z) : t;
}

__device__ __forceinline__ unsigned cmp3(float d, float df, float da, float dfa) {
    return (unsigned)(df >= d) & (unsigned)(da < d) & (unsigned)(dfa < d);
}

// ---------------- Kernel A: step-1 mask + step-1 ch0/ch1, 2x4-wide ----------------
__device__ __forceinline__ void kA_lane(
    float dm, float d, float dp, float dfm, float dfc, float dfp,
    float e0m, float e0c, float e0p,
    unsigned& a1, unsigned& e1, float& d1)
{
    a1 = (unsigned)(e0c == 3.0f) & cmp3(d, dfc, dm, dfm);
    unsigned b1 = (unsigned)(e0p == 3.0f) & cmp3(dp, dfp, d, dfc);
    float e1v = selv(a1 != 0u, b1 != 0u, e0m, e0c, e0p);
    d1        = selv(a1 != 0u, b1 != 0u, dm,  d,   dp);
    e1 = (unsigned)(e1v == 3.0f);
}

// process one float4 vector given its own c1/c0 rows and the previous vector's c1 rows
__device__ __forceinline__ void kA_vec(
    float4 c1m, float4 c1c, float4 c1p,          // ch1 rows hm,h,hp at this col
    float pm, float pc, float pp,                // ch1 rows at (w-1): prev vector's .w
    float4 c0m, float4 c0c, float4 c0p,          // ch0 rows hm,h,hp at this col
    unsigned& a1w, unsigned& e1w, float4& d1v)
{
    unsigned a, e; float dd;
    a1w = 0; e1w = 0;
    kA_lane(c1m.x, c1c.x, c1p.x, pm, pc, pp, c0m.x, c0c.x, c0p.x, a, e, dd);
    a1w |= a; e1w |= e; d1v.x = dd;
    kA_lane(c1m.y, c1c.y, c1p.y, c1m.x, c1c.x, c1p.x, c0m.y, c0c.y, c0p.y, a, e, dd);
    a1w |= a << 8; e1w |= e << 8; d1v.y = dd;
    kA_lane(c1m.z, c1c.z, c1p.z, c1m.y, c1c.y, c1p.y, c0m.z, c0c.z, c0p.z, a, e, dd);
    a1w |= a << 16; e1w |= e << 16; d1v.z = dd;
    kA_lane(c1m.w, c1c.w, c1p.w, c1m.z, c1c.z, c1p.z, c0m.w, c0c.w, c0p.w, a, e, dd);
    a1w |= a << 24; e1w |= e << 24; d1v.w = dd;
}

__global__ void kA(const float* __restrict__ world) {
    int idx = blockIdx.x * blockDim.x + threadIdx.x;   // b<<15 | h<<6 | wp
    int wp = idx & 63;                 // pair index
    int h  = (idx >> 6) & HMASK;
    int b  = idx >> 15;
    int w4a = wp * 2;
    int w4b = w4a + 1;
    int hm = (h - 1) & HMASK, hp = (h + 1) & HMASK;
    int w4m = (w4a - 1) & W4MASK;

    const float4* c0 = (const float4*)(world + (long)b * CHWn);
    const float4* c1 = c0 + HW4n;

    // 9 ch1 loads (prev, A, B) x 3 rows; 6 ch0 loads (A, B) x 3 rows
    float4 c1mP = c1[hm * W4n + w4m], c1cP = c1[h * W4n + w4m], c1pP = c1[hp * W4n + w4m];
    float4 c1mA = c1[hm * W4n + w4a], c1cA = c1[h * W4n + w4a], c1pA = c1[hp * W4n + w4a];
    float4 c1mB = c1[hm * W4n + w4b], c1cB = c1[h * W4n + w4b], c1pB = c1[hp * W4n + w4b];
    float4 c0mA = c0[hm * W4n + w4a], c0cA = c0[h * W4n + w4a], c0pA = c0[hp * W4n + w4a];
    float4 c0mB = c0[hm * W4n + w4b], c0cB = c0[h * W4n + w4b], c0pB = c0[hp * W4n + w4b];

    unsigned a1w, e1w; float4 d1v;
    int idxA = (b << 16) | (h << 7) | w4a;

    kA_vec(c1mA, c1cA, c1pA, c1mP.w, c1cP.w, c1pP.w, c0mA, c0cA, c0pA, a1w, e1w, d1v);
    g_a1[idxA] = a1w; g_e1[idxA] = e1w; g_d1[idxA] = d1v;

    kA_vec(c1mB, c1cB, c1pB, c1mA.w, c1cA.w, c1pA.w, c0mB, c0cB, c0pB, a1w, e1w, d1v);
    g_a1[idxA + 1] = a1w; g_e1[idxA + 1] = e1w; g_d1[idxA + 1] = d1v;
}

// ---------------- Kernel B: step-2 mask + packed per-pixel control byte ----------------
__global__ void kB() {
    int idx = blockIdx.x * blockDim.x + threadIdx.x;
    int w4 = idx & W4MASK;
    int h  = (idx >> 7) & HMASK;
    int b  = idx >> 16;
    int hm = (h - 1) & HMASK, hp = (h + 1) & HMASK;
    int w4p = (w4 + 1) & W4MASK;
    int base = b << 16;

    const float4* d1 = g_d1 + base;
    float4 dm = d1[hm * W4n + w4],  dc = d1[h * W4n + w4],  dp = d1[hp * W4n + w4];
    float4 dmN = d1[hm * W4n + w4p], dcN = d1[h * W4n + w4p], dpN = d1[hp * W4n + w4p];
    unsigned e1c = g_e1[idx];
    unsigned e1p = g_e1[base + hp * W4n + w4];
    unsigned a1c = g_a1[idx];
    unsigned a1p = g_a1[base + hp * W4n + w4];

    unsigned a2c = ((e1c)        & 1u) & cmp3(dc.x, dc.y, dm.x, dm.y);
    a2c |= (((e1c >> 8)  & 1u) & cmp3(dc.y, dc.z, dm.y, dm.z)) << 8;
    a2c |= (((e1c >> 16) & 1u) & cmp3(dc.z, dc.w, dm.z, dm.w)) << 16;
    a2c |= (((e1c >> 24) & 1u) & cmp3(dc.w, dcN.x, dm.w, dmN.x)) << 24;

    unsigned a2p = ((e1p)        & 1u) & cmp3(dp.x, dp.y, dc.x, dc.y);
    a2p |= (((e1p >> 8)  & 1u) & cmp3(dp.y, dp.z, dc.y, dc.z)) << 8;
    a2p |= (((e1p >> 16) & 1u) & cmp3(dp.z, dp.w, dc.z, dc.w)) << 16;
    a2p |= (((e1p >> 24) & 1u) & cmp3(dp.w, dpN.x, dc.w, dcN.x)) << 24;

    g_code[idx] = a1c | (a1p << 1) | (a2c << 2) | (a2p << 3);
}

// ---------------- Kernel C: fused two-step apply, 2 channels/thread ----------------
#define NCH 8
#define CHUNK (Hn / NCH)   // 64

// w1 select (bits 0,1 per byte) for two channels sharing the predicates
__device__ __forceinline__ void w1vec2(unsigned cw,
    float4 a0, float4 b0, float4 c0, float4 a1, float4 b1, float4 c1,
    float4& o0, float4& o1)
{
    bool px, qx = cw & 0x00000002u; px = cw & 0x00000001u;
    o0.x = selv(px, qx, a0.x, b0.x, c0.x); o1.x = selv(px, qx, a1.x, b1.x, c1.x);
    px = cw & 0x00000100u; qx = cw & 0x00000200u;
    o0.y = selv(px, qx, a0.y, b0.y, c0.y); o1.y = selv(px, qx, a1.y, b1.y, c1.y);
    px = cw & 0x00010000u; qx = cw & 0x00020000u;
    o0.z = selv(px, qx, a0.z, b0.z, c0.z); o1.z = selv(px, qx, a1.z, b1.z, c1.z);
    px = cw & 0x01000000u; qx = cw & 0x02000000u;
    o0.w = selv(px, qx, a0.w, b0.w, c0.w); o1.w = selv(px, qx, a1.w, b1.w, c1.w);
}

// final select (bits 2,3 per byte) for two channels sharing the predicates
__device__ __forceinline__ void outvec2(unsigned cw,
    float4 a0, float4 b0, float4 c0, float4 a1, float4 b1, float4 c1,
    float4& o0, float4& o1)
{
    bool px, qx = cw & 0x00000008u; px = cw & 0x00000004u;
    o0.x = selv(px, qx, a0.x, b0.x, c0.x); o1.x = selv(px, qx, a1.x, b1.x, c1.x);
    px = cw & 0x00000400u; qx = cw & 0x00000800u;
    o0.y = selv(px, qx, a0.y, b0.y, c0.y); o1.y = selv(px, qx, a1.y, b1.y, c1.y);
    px = cw & 0x00040000u; qx = cw & 0x00080000u;
    o0.z = selv(px, qx, a0.z, b0.z, c0.z); o1.z = selv(px, qx, a1.z, b1.z, c1.z);
    px = cw & 0x04000000u; qx = cw & 0x08000000u;
    o0.w = selv(px, qx, a0.w, b0.w, c0.w); o1.w = selv(px, qx, a1.w, b1.w, c1.w);
}

__global__ void __launch_bounds__(128, 4) kC(const float* __restrict__ world,
                                             float* __restrict__ out) {
    int w4 = threadIdx.x;                 // 0..127 — full row of float4
    int h0 = blockIdx.y * CHUNK;
    int bc = blockIdx.z;                  // 0..159: b * 10 + channel-pair
    int b  = bc / (Cn / 2);
    int cp = bc - b * (Cn / 2);
    int c0i = cp * 2;

    const float4* pA = (const float4*)(world + (long)b * CHWn + (long)c0i * HWn);
    const float4* pB = pA + HW4n;
    float4* qA = (float4*)(out + (long)b * CHWn + (long)c0i * HWn);
    float4* qB = qA + HW4n;
    const unsigned* ck = g_code + (b << 16);

    // rolling world rows h-2..h+2, both channels
    float4 a0 = __ldcs(pA + ((h0 - 2) & HMASK) * W4n + w4);
    float4 a1 = __ldcs(pA + ((h0 - 1) & HMASK) * W4n + w4);
    float4 a2 = __ldcs(pA + h0 * W4n + w4);
    float4 a3 = __ldcs(pA + ((h0 + 1) & HMASK) * W4n + w4);
    float4 a4 = __ldcs(pA + ((h0 + 2) & HMASK) * W4n + w4);
    float4 b0 = __ldcs(pB + ((h0 - 2) & HMASK) * W4n + w4);
    float4 b1 = __ldcs(pB + ((h0 - 1) & HMASK) * W4n + w4);
    float4 b2 = __ldcs(pB + h0 * W4n + w4);
    float4 b3 = __ldcs(pB + ((h0 + 1) & HMASK) * W4n + w4);
    float4 b4 = __ldcs(pB + ((h0 + 2) & HMASK) * W4n + w4);

    unsigned cm = ck[((h0 - 1) & HMASK) * W4n + w4];
    unsigned cc = ck[h0 * W4n + w4];
    unsigned cpw = ck[((h0 + 1) & HMASK) * W4n + w4];

    // w1 windows for both channels: rows h0-1, h0, h0+1
    float4 sA0, sA1, sA2, sB0, sB1, sB2;
    w1vec2(cm,  a0, a1, a2, b0, b1, b2, sA0, sB0);
    w1vec2(cc,  a1, a2, a3, b1, b2, b3, sA1, sB1);
    w1vec2(cpw, a2, a3, a4, b2, b3, b4, sA2, sB2);

#pragma unroll 4
    for (int hh = 0; hh < CHUNK; hh++) {
        int h = h0 + hh;
        float4 rnA = __ldcs(pA + ((h + 3) & HMASK) * W4n + w4);
        float4 rnB = __ldcs(pB + ((h + 3) & HMASK) * W4n + w4);
        unsigned cn = ck[((h + 2) & HMASK) * W4n + w4];

        float4 oA, oB;
        outvec2(cc, sA0, sA1, sA2, sB0, sB1, sB2, oA, oB);
        __stcs(qA + h * W4n + w4, oA);
        __stcs(qB + h * W4n + w4, oB);

        a0 = a1; a1 = a2; a2 = a3; a3 = a4; a4 = rnA;
        b0 = b1; b1 = b2; b2 = b3; b3 = b4; b4 = rnB;
        sA0 = sA1; sA1 = sA2; sB0 = sB1; sB1 = sB2;
        w1vec2(cn, a2, a3, a4, b2, b3, b4, sA2, sB2);   // w1[h+2]
        cc = cpw; cpw = cn;
    }
}

extern "C" void kernel_launch(void* const* d_in, const int* in_sizes, int n_in,
                              void* d_out, int out_size) {
    const float* world = (const float*)d_in[0];   // (16,20,512,512) fp32
    float* out = (float*)d_out;

    int npair = Bn * Hn * (W4n / 2);      // 524,288
    kA<<<npair / 256, 256>>>(world);
    int nvec = Bn * HW4n;                 // 1,048,576
    kB<<<nvec / 256, 256>>>();

    dim3 grid(1, NCH, Bn * (Cn / 2));     // (1, 8, 160)
    kC<<<grid, 128>>>(world, out);
}

// round 9
// speedup vs baseline: 1.2340x; 1.2340x over previous
#include <cuda_runtime.h>

#define Bn 16
#define Cn 20
#define Hn 512
#define Wn 512
#define W4n (Wn / 4)
#define HWn (Hn * Wn)
#define HW4n (Hn * W4n)
#define CHWn (Cn * HWn)
#define HMASK (Hn - 1)
#define W4MASK (W4n - 1)

// Scratch (__device__ globals per allocation-free rule)
__device__ unsigned g_a1[Bn * HW4n];    // step-1 mask, 1 byte/pixel (0/1)
__device__ unsigned g_e1[Bn * HW4n];    // (world1 ch0 == 3) flag, packed
__device__ float4   g_d1[Bn * HW4n];    // world1 ch1 (density after step 1)
__device__ unsigned g_code[Bn * HW4n];  // per byte: a1[h] | a1[h+1]<<1 | a2[h]<<2 | a2[h+1]<<3

// exact 0/1-coefficient blend, BRANCHLESS: (1-a)(1-b)y + a*x + b*z
__device__ __forceinline__ float selv(bool a, bool b, float x, float y, float z) {
    float t = b ? z : y;
    t = a ? x : t;
    return (a && b) ? (x + z) : t;
}

__device__ __forceinline__ unsigned cmp3(float d, float df, float da, float dfa) {
    return (unsigned)(df >= d) & (unsigned)(da < d) & (unsigned)(dfa < d);
}

// ---------------- Kernel A: step-1 mask + step-1 ch0/ch1, 4-wide (R6 version) ----------------
__device__ __forceinline__ void kA_lane(
    float dm, float d, float dp, float dfm, float dfc, float dfp,
    float e0m, float e0c, float e0p,
    unsigned& a1, unsigned& e1, float& d1)
{
    a1 = (unsigned)(e0c == 3.0f) & cmp3(d, dfc, dm, dfm);
    unsigned b1 = (unsigned)(e0p == 3.0f) & cmp3(dp, dfp, d, dfc);
    float e1v = selv(a1 != 0u, b1 != 0u, e0m, e0c, e0p);
    d1        = selv(a1 != 0u, b1 != 0u, dm,  d,   dp);
    e1 = (unsigned)(e1v == 3.0f);
}

__global__ void kA(const float* __restrict__ world) {
    int idx = blockIdx.x * blockDim.x + threadIdx.x;   // b<<16 | h<<7 | w4
    int w4 = idx & W4MASK;
    int h  = (idx >> 7) & HMASK;
    int b  = idx >> 16;
    int hm = (h - 1) & HMASK, hp = (h + 1) & HMASK;
    int w4m = (w4 - 1) & W4MASK;

    const float4* c0 = (const float4*)(world + (long)b * CHWn);
    const float4* c1 = c0 + HW4n;

    float4 c1m = c1[hm * W4n + w4], c1c = c1[h * W4n + w4], c1p = c1[hp * W4n + w4];
    float4 c1mP = c1[hm * W4n + w4m], c1cP = c1[h * W4n + w4m], c1pP = c1[hp * W4n + w4m];
    float4 c0m = c0[hm * W4n + w4], c0c = c0[h * W4n + w4], c0p = c0[hp * W4n + w4];

    unsigned a1w = 0, e1w = 0;
    float4 d1v;
    unsigned a, e; float dd;

    kA_lane(c1m.x, c1c.x, c1p.x, c1mP.w, c1cP.w, c1pP.w, c0m.x, c0c.x, c0p.x, a, e, dd);
    a1w |= a; e1w |= e; d1v.x = dd;
    kA_lane(c1m.y, c1c.y, c1p.y, c1m.x, c1c.x, c1p.x, c0m.y, c0c.y, c0p.y, a, e, dd);
    a1w |= a << 8; e1w |= e << 8; d1v.y = dd;
    kA_lane(c1m.z, c1c.z, c1p.z, c1m.y, c1c.y, c1p.y, c0m.z, c0c.z, c0p.z, a, e, dd);
    a1w |= a << 16; e1w |= e << 16; d1v.z = dd;
    kA_lane(c1m.w, c1c.w, c1p.w, c1m.z, c1c.z, c1p.z, c0m.w, c0c.w, c0p.w, a, e, dd);
    a1w |= a << 24; e1w |= e << 24; d1v.w = dd;

    g_a1[idx] = a1w;
    g_e1[idx] = e1w;
    g_d1[idx] = d1v;
}

// ---------------- Kernel B: step-2 mask + packed per-pixel control byte ----------------
__global__ void kB() {
    int idx = blockIdx.x * blockDim.x + threadIdx.x;
    int w4 = idx & W4MASK;
    int h  = (idx >> 7) & HMASK;
    int b  = idx >> 16;
    int hm = (h - 1) & HMASK, hp = (h + 1) & HMASK;
    int w4p = (w4 + 1) & W4MASK;
    int base = b << 16;

    const float4* d1 = g_d1 + base;
    float4 dm = d1[hm * W4n + w4],  dc = d1[h * W4n + w4],  dp = d1[hp * W4n + w4];
    float4 dmN = d1[hm * W4n + w4p], dcN = d1[h * W4n + w4p], dpN = d1[hp * W4n + w4p];
    unsigned e1c = g_e1[idx];
    unsigned e1p = g_e1[base + hp * W4n + w4];
    unsigned a1c = g_a1[idx];
    unsigned a1p = g_a1[base + hp * W4n + w4];

    unsigned a2c = ((e1c)        & 1u) & cmp3(dc.x, dc.y, dm.x, dm.y);
    a2c |= (((e1c >> 8)  & 1u) & cmp3(dc.y, dc.z, dm.y, dm.z)) << 8;
    a2c |= (((e1c >> 16) & 1u) & cmp3(dc.z, dc.w, dm.z, dm.w)) << 16;
    a2c |= (((e1c >> 24) & 1u) & cmp3(dc.w, dcN.x, dm.w, dmN.x)) << 24;

    unsigned a2p = ((e1p)        & 1u) & cmp3(dp.x, dp.y, dc.x, dc.y);
    a2p |= (((e1p >> 8)  & 1u) & cmp3(dp.y, dp.z, dc.y, dc.z)) << 8;
    a2p |= (((e1p >> 16) & 1u) & cmp3(dp.z, dp.w, dc.z, dc.w)) << 16;
    a2p |= (((e1p >> 24) & 1u) & cmp3(dp.w, dpN.x, dc.w, dcN.x)) << 24;

    g_code[idx] = a1c | (a1p << 1) | (a2c << 2) | (a2p << 3);
}

// ---------------- Kernel C: fused two-step apply, 4-row batched loads ----------------
#define NCH 8
#define CHUNK (Hn / NCH)   // 64

__device__ __forceinline__ float4 w1vec(unsigned cw, float4 a, float4 b, float4 c) {
    float4 o;
    o.x = selv(cw & 0x00000001u, cw & 0x00000002u, a.x, b.x, c.x);
    o.y = selv(cw & 0x00000100u, cw & 0x00000200u, a.y, b.y, c.y);
    o.z = selv(cw & 0x00010000u, cw & 0x00020000u, a.z, b.z, c.z);
    o.w = selv(cw & 0x01000000u, cw & 0x02000000u, a.w, b.w, c.w);
    return o;
}
__device__ __forceinline__ float4 outvec(unsigned cw, float4 a, float4 b, float4 c) {
    float4 o;
    o.x = selv(cw & 0x00000004u, cw & 0x00000008u, a.x, b.x, c.x);
    o.y = selv(cw & 0x00000400u, cw & 0x00000800u, a.y, b.y, c.y);
    o.z = selv(cw & 0x00040000u, cw & 0x00080000u, a.z, b.z, c.z);
    o.w = selv(cw & 0x04000000u, cw & 0x08000000u, a.w, b.w, c.w);
    return o;
}

__global__ void __launch_bounds__(128, 8) kC(const float* __restrict__ world,
                                             float* __restrict__ out) {
    int w4 = threadIdx.x;                 // 0..127 — full row of float4
    int h0 = blockIdx.y * CHUNK;
    int bc = blockIdx.z;
    int b = bc / Cn;
    int c = bc - b * Cn;

    const float4* p = (const float4*)(world + (long)b * CHWn + (long)c * HWn);
    float4*       q = (float4*)(out + (long)b * CHWn + (long)c * HWn);
    const unsigned* ck = g_code + (b << 16);

    float4 r0 = p[((h0 - 2) & HMASK) * W4n + w4];
    float4 r1 = p[((h0 - 1) & HMASK) * W4n + w4];
    float4 r2 = p[h0 * W4n + w4];
    float4 r3 = p[((h0 + 1) & HMASK) * W4n + w4];
    float4 r4 = p[((h0 + 2) & HMASK) * W4n + w4];

    unsigned cm = ck[((h0 - 1) & HMASK) * W4n + w4];
    unsigned cc = ck[h0 * W4n + w4];
    unsigned cp = ck[((h0 + 1) & HMASK) * W4n + w4];

    float4 t0 = w1vec(cm, r0, r1, r2);   // w1[h0-1]
    float4 t1 = w1vec(cc, r1, r2, r3);   // w1[h0]
    float4 t2 = w1vec(cp, r2, r3, r4);   // w1[h0+1]

    for (int hh = 0; hh < CHUNK; hh += 4) {
        int h = h0 + hh;
        // ---- front-batched loads for the next 4 rows (MLP) ----
        float4 L0 = p[((h + 3) & HMASK) * W4n + w4];
        float4 L1 = p[((h + 4) & HMASK) * W4n + w4];
        float4 L2 = p[((h + 5) & HMASK) * W4n + w4];
        float4 L3 = p[((h + 6) & HMASK) * W4n + w4];
        unsigned C0 = ck[((h + 2) & HMASK) * W4n + w4];
        unsigned C1 = ck[((h + 3) & HMASK) * W4n + w4];
        unsigned C2 = ck[((h + 4) & HMASK) * W4n + w4];
        unsigned C3 = ck[((h + 5) & HMASK) * W4n + w4];

        // row h
        __stcs(q + h * W4n + w4, outvec(cc, t0, t1, t2));
        r0 = r1; r1 = r2; r2 = r3; r3 = r4; r4 = L0;
        t0 = t1; t1 = t2; t2 = w1vec(C0, r2, r3, r4);
        cc = cp; cp = C0;

        // row h+1
        __stcs(q + (h + 1) * W4n + w4, outvec(cc, t0, t1, t2));
        r0 = r1; r1 = r2; r2 = r3; r3 = r4; r4 = L1;
        t0 = t1; t1 = t2; t2 = w1vec(C1, r2, r3, r4);
        cc = cp; cp = C1;

        // row h+2
        __stcs(q + (h + 2) * W4n + w4, outvec(cc, t0, t1, t2));
        r0 = r1; r1 = r2; r2 = r3; r3 = r4; r4 = L2;
        t0 = t1; t1 = t2; t2 = w1vec(C2, r2, r3, r4);
        cc = cp; cp = C2;

        // row h+3
        __stcs(q + (h + 3) * W4n + w4, outvec(cc, t0, t1, t2));
        r0 = r1; r1 = r2; r2 = r3; r3 = r4; r4 = L3;
        t0 = t1; t1 = t2; t2 = w1vec(C3, r2, r3, r4);
        cc = cp; cp = C3;
    }
}

extern "C" void kernel_launch(void* const* d_in, const int* in_sizes, int n_in,
                              void* d_out, int out_size) {
    const float* world = (const float*)d_in[0];   // (16,20,512,512) fp32
    float* out = (float*)d_out;

    int nvec = Bn * HW4n;                 // 1,048,576
    kA<<<nvec / 256, 256>>>(world);
    kB<<<nvec / 256, 256>>>();

    dim3 grid(1, NCH, Bn * Cn);           // (1, 8, 320)
    kC<<<grid, 128>>>(world, out);
}